// round 6
// baseline (speedup 1.0000x reference)
#include <cuda_runtime.h>
#include <cuda_bf16.h>
#include <stdint.h>

// Shapes: bs=16384, din=512, mid=1024, out=512, K=2, D1=2, D2=4
//
// Two bf16 split-precision GEMMs via mma.sync (plain PTX under compute_103):
//   A1 (bs x 1024)  = interleave(q1_0, x)
//   h1 (bs x 1024)  = bn1(relu(A1 @ w1^T + b1))
//   A2 (bs x 3072)  = [q2_0 (1024) | h1 (1024) | A1 (1024)]   (K-reordered)
//   WC (512 x 3072) = [w2 even cols | w2 odd cols | w_skip]
//   out (bs x 512)  = bn2(relu(A2 @ WC^T + b2 + b_skip))
// Split precision, fused single K-pass: Ah*Bh + Al*Bh + Ah*Bl (drop Al*Bl ~2^-16).
// CTA tile 256x128 (BK=64), 2-stage cp.async pipeline, warp tile 64x64.

#define BSZ   16384
#define KD1   1024
#define KD2   3072
#define NMID  1024
#define NOUT  512
#define EPSBN 1e-5f

#define BM 256
#define BN 128
#define BK 64                           // bf16 elems -> 128B rows
#define STAGES 2
#define A_TILE_BYTES (256 * 128)        // 32 KB
#define B_TILE_BYTES (128 * 128)        // 16 KB
#define STAGE_BYTES  (2*A_TILE_BYTES + 2*B_TILE_BYTES)   // 96 KB: Ah|Al|Bh|Bl
#define OFF_AL (A_TILE_BYTES)
#define OFF_BH (2*A_TILE_BYTES)
#define OFF_BL (2*A_TILE_BYTES + B_TILE_BYTES)
#define SMEM_BYTES (STAGES * STAGE_BYTES)                // 192 KB

// ---------------------------------------------------------------------------
// Scratch (static device arrays: allocation-free)
// ---------------------------------------------------------------------------
static __device__ __nv_bfloat16 g_A1h[(size_t)BSZ*KD1];
static __device__ __nv_bfloat16 g_A1l[(size_t)BSZ*KD1];
static __device__ __nv_bfloat16 g_A2h[(size_t)BSZ*KD2];
static __device__ __nv_bfloat16 g_A2l[(size_t)BSZ*KD2];
static __device__ __nv_bfloat16 g_W1h[(size_t)NMID*KD1];
static __device__ __nv_bfloat16 g_W1l[(size_t)NMID*KD1];
static __device__ __nv_bfloat16 g_WCh[(size_t)NOUT*KD2];
static __device__ __nv_bfloat16 g_WCl[(size_t)NOUT*KD2];

// ---------------------------------------------------------------------------
// PTX helpers (plain sm_80-era PTX)
// ---------------------------------------------------------------------------
__device__ __forceinline__ uint32_t smem_u32(const void* p) {
    uint32_t a;
    asm("{ .reg .u64 t; cvta.to.shared.u64 t, %1; cvt.u32.u64 %0, t; }" : "=r"(a) : "l"(p));
    return a;
}
__device__ __forceinline__ void cp16(uint32_t s, const void* g) {
    asm volatile("cp.async.cg.shared.global [%0], [%1], 16;" :: "r"(s), "l"(g));
}
__device__ __forceinline__ void cp_commit() {
    asm volatile("cp.async.commit_group;" ::: "memory");
}
__device__ __forceinline__ void cp_wait1() {
    asm volatile("cp.async.wait_group 1;" ::: "memory");
}
__device__ __forceinline__ void cp_wait0() {
    asm volatile("cp.async.wait_group 0;" ::: "memory");
}
__device__ __forceinline__ void ldm4(uint32_t& r0, uint32_t& r1, uint32_t& r2, uint32_t& r3,
                                     uint32_t addr) {
    asm volatile("ldmatrix.sync.aligned.m8n8.x4.shared.b16 {%0,%1,%2,%3}, [%4];"
                 : "=r"(r0), "=r"(r1), "=r"(r2), "=r"(r3) : "r"(addr));
}
__device__ __forceinline__ void mma16816(float* c, const uint32_t* a, const uint32_t* b) {
    asm volatile("mma.sync.aligned.m16n8k16.row.col.f32.bf16.bf16.f32 "
                 "{%0,%1,%2,%3}, {%4,%5,%6,%7}, {%8,%9}, {%0,%1,%2,%3};"
                 : "+f"(c[0]), "+f"(c[1]), "+f"(c[2]), "+f"(c[3])
                 : "r"(a[0]), "r"(a[1]), "r"(a[2]), "r"(a[3]), "r"(b[0]), "r"(b[1]));
}
__device__ __forceinline__ uint32_t sw128(uint32_t o) { return o ^ ((o >> 3) & 0x70); }

__device__ __forceinline__ void bsplit(float v, __nv_bfloat16& h, __nv_bfloat16& l) {
    h = __float2bfloat16(v);
    l = __float2bfloat16(v - __bfloat162float(h));
}

// ---------------------------------------------------------------------------
// Single merged pack kernel (fp32 -> bf16 hi/lo), range-partitioned
// ---------------------------------------------------------------------------
#define NP0 (BSZ * 512)           // a1 pairs
#define NP1 (BSZ * 512)           // a2q pairs
#define NP2 (NMID * KD1 / 2)      // w1 pairs
#define NP3 (NOUT * KD2)          // wcat singles
#define NPTOT (NP0 + NP1 + NP2 + NP3)

__global__ void pack_all(const float* __restrict__ q1, const float* __restrict__ x,
                         const float* __restrict__ q2, const float* __restrict__ w1,
                         const float* __restrict__ w2, const float* __restrict__ wsk) {
    int i = blockIdx.x * blockDim.x + threadIdx.x;
    if (i < NP0) {
        // A1[m, 2c]=q1_0[m,c], A1[m, 2c+1]=x[m,c]; also copy into A2 cols 2048+
        int m = i >> 9, c = i & 511;
        __nv_bfloat16 h0, l0, h1, l1;
        bsplit(q1[i], h0, l0);
        bsplit(x[i],  h1, l1);
        __nv_bfloat162 hp = __halves2bfloat162(h0, h1);
        __nv_bfloat162 lp = __halves2bfloat162(l0, l1);
        size_t o1 = (size_t)m * KD1 + 2 * c;
        *reinterpret_cast<__nv_bfloat162*>(&g_A1h[o1]) = hp;
        *reinterpret_cast<__nv_bfloat162*>(&g_A1l[o1]) = lp;
        size_t o2 = (size_t)m * KD2 + 2048 + 2 * c;
        *reinterpret_cast<__nv_bfloat162*>(&g_A2h[o2]) = hp;
        *reinterpret_cast<__nv_bfloat162*>(&g_A2l[o2]) = lp;
    } else if (i < NP0 + NP1) {
        int j = i - NP0;
        int m = j >> 9, c2 = (j & 511) * 2;
        float2 v = reinterpret_cast<const float2*>(q2)[j];
        __nv_bfloat16 h0, l0, h1, l1;
        bsplit(v.x, h0, l0);
        bsplit(v.y, h1, l1);
        size_t o = (size_t)m * KD2 + c2;
        *reinterpret_cast<__nv_bfloat162*>(&g_A2h[o]) = __halves2bfloat162(h0, h1);
        *reinterpret_cast<__nv_bfloat162*>(&g_A2l[o]) = __halves2bfloat162(l0, l1);
    } else if (i < NP0 + NP1 + NP2) {
        int j = i - NP0 - NP1;
        float2 v = reinterpret_cast<const float2*>(w1)[j];
        __nv_bfloat16 h0, l0, h1, l1;
        bsplit(v.x, h0, l0);
        bsplit(v.y, h1, l1);
        *reinterpret_cast<__nv_bfloat162*>(&g_W1h[2*j]) = __halves2bfloat162(h0, h1);
        *reinterpret_cast<__nv_bfloat162*>(&g_W1l[2*j]) = __halves2bfloat162(l0, l1);
    } else if (i < NPTOT) {
        int j = i - NP0 - NP1 - NP2;
        int n = j / KD2, c = j - n * KD2;
        float v;
        if (c < 1024)       v = w2[(size_t)n * 2048 + 2 * c];               // pairs q2
        else if (c < 2048)  v = w2[(size_t)n * 2048 + 2 * (c - 1024) + 1];  // pairs h1
        else                v = wsk[(size_t)n * 1024 + (c - 2048)];         // skip
        __nv_bfloat16 h, l;
        bsplit(v, h, l);
        g_WCh[j] = h; g_WCl[j] = l;
    }
}

// ---------------------------------------------------------------------------
// Fused 3-term mma.sync GEMM: 256x128 CTA, BK=64, 2-stage cp.async pipeline.
// 8 warps: warp_m = wid&3 (64 rows), warp_n = wid>>2 (64 cols).
// MODE 0: A1 @ W1^T  -> h1 (bf16 hi/lo) into A2 cols 1024..2047
// MODE 1: A2 @ WC^T  -> fp32 out
// ---------------------------------------------------------------------------
template<int MODE>
__global__ void __launch_bounds__(256) gemm_kernel(
    const float* __restrict__ pb0, const float* __restrict__ pb1,
    const float* __restrict__ psc, const float* __restrict__ pbi,
    const float* __restrict__ pmu, const float* __restrict__ pva,
    float* __restrict__ outp)
{
    extern __shared__ __align__(1024) char smem[];
    const uint32_t sb = smem_u32(smem);
    const int tid = threadIdx.x;
    const int wid = tid >> 5, lane = tid & 31;
    const int warp_m = wid & 3;      // 0..3 -> 64-row slices of 256
    const int warp_n = wid >> 2;     // 0..1 -> 64-col slices of 128
    const int blockRow = blockIdx.y * BM, blockCol = blockIdx.x * BN;

    constexpr int KDIM = (MODE == 0) ? KD1 : KD2;
    constexpr int KC   = KDIM / BK;

    const __nv_bfloat16* Ah = (MODE == 0) ? g_A1h : g_A2h;
    const __nv_bfloat16* Al = (MODE == 0) ? g_A1l : g_A2l;
    const __nv_bfloat16* Bh = (MODE == 0) ? g_W1h : g_WCh;
    const __nv_bfloat16* Bl = (MODE == 0) ? g_W1l : g_WCl;

    // cp.async: A tiles: thread t loads full 128B row t (8x cp16).
    //           B tiles: thread t loads half of row t/2 (4x cp16 each tile).
    const __nv_bfloat16* ArH = Ah + (size_t)(blockRow + tid) * KDIM;
    const __nv_bfloat16* ArL = Al + (size_t)(blockRow + tid) * KDIM;
    const int brow = tid >> 1, bhalf = tid & 1;
    const __nv_bfloat16* BrH = Bh + (size_t)(blockCol + brow) * KDIM + bhalf * 32;
    const __nv_bfloat16* BrL = Bl + (size_t)(blockCol + brow) * KDIM + bhalf * 32;
    uint32_t aoff[8], boff[4];
    #pragma unroll
    for (int i = 0; i < 8; i++) aoff[i] = sw128((uint32_t)tid * 128u + (uint32_t)i * 16u);
    #pragma unroll
    for (int i = 0; i < 4; i++)
        boff[i] = sw128((uint32_t)brow * 128u + (uint32_t)(bhalf * 4 + i) * 16u);

    auto load_chunk = [&](int j) {
        const char* gah = (const char*)(ArH + j * BK);
        const char* gal = (const char*)(ArL + j * BK);
        const char* gbh = (const char*)(BrH + j * BK);
        const char* gbl = (const char*)(BrL + j * BK);
        uint32_t bs_ = sb + (uint32_t)(j & 1) * STAGE_BYTES;
        #pragma unroll
        for (int i = 0; i < 8; i++) cp16(bs_ +          aoff[i], gah + i * 16);
        #pragma unroll
        for (int i = 0; i < 8; i++) cp16(bs_ + OFF_AL + aoff[i], gal + i * 16);
        #pragma unroll
        for (int i = 0; i < 4; i++) cp16(bs_ + OFF_BH + boff[i], gbh + i * 16);
        #pragma unroll
        for (int i = 0; i < 4; i++) cp16(bs_ + OFF_BL + boff[i], gbl + i * 16);
    };

    float acc[4][8][4] = {};    // [mtile(16r)][ntile(8c)][frag]

    const int lrow16 = lane & 15;
    const int lhalf  = lane >> 4;

    load_chunk(0); cp_commit();

    for (int i = 0; i < KC; i++) {
        if (i + 1 < KC) { load_chunk(i + 1); cp_commit(); cp_wait1(); }
        else            { cp_wait0(); }
        __syncthreads();

        uint32_t st  = sb + (uint32_t)(i & 1) * STAGE_BYTES;
        uint32_t sAh = st, sAl = st + OFF_AL, sBh = st + OFF_BH, sBl = st + OFF_BL;

        #pragma unroll
        for (int k16 = 0; k16 < 4; k16++) {
            const uint32_t chunk = (uint32_t)(k16 * 2 + lhalf) * 16u;
            uint32_t ah[4][4], al[4][4];
            #pragma unroll
            for (int it = 0; it < 4; it++) {
                uint32_t ro = sw128((uint32_t)(warp_m * 64 + it * 16 + lrow16) * 128u + chunk);
                ldm4(ah[it][0], ah[it][1], ah[it][2], ah[it][3], sAh + ro);
                ldm4(al[it][0], al[it][1], al[it][2], al[it][3], sAl + ro);
            }
            #pragma unroll
            for (int jn = 0; jn < 4; jn++) {     // 16 N-rows each -> 2 n8 frags
                uint32_t rob = sw128((uint32_t)(warp_n * 64 + jn * 16 + lrow16) * 128u + chunk);
                uint32_t r0, r1, r2, r3;
                uint32_t bh0[2], bh1[2], bl0[2], bl1[2];
                ldm4(r0, r1, r2, r3, sBh + rob);
                bh0[0] = r0; bh0[1] = r2; bh1[0] = r1; bh1[1] = r3;
                ldm4(r0, r1, r2, r3, sBl + rob);
                bl0[0] = r0; bl0[1] = r2; bl1[0] = r1; bl1[1] = r3;
                #pragma unroll
                for (int it = 0; it < 4; it++) {
                    mma16816(acc[it][2*jn],   ah[it], bh0);
                    mma16816(acc[it][2*jn+1], ah[it], bh1);
                    mma16816(acc[it][2*jn],   al[it], bh0);
                    mma16816(acc[it][2*jn+1], al[it], bh1);
                    mma16816(acc[it][2*jn],   ah[it], bl0);
                    mma16816(acc[it][2*jn+1], ah[it], bl1);
                }
            }
        }
        __syncthreads();    // guard stage reuse by next iteration's load
    }

    // ------------------- epilogue -------------------
    float* sp = (float*)smem;
    if (tid < BN) {
        int n = blockCol + tid;
        float se = psc[n] * rsqrtf(pva[n] + EPSBN);
        sp[tid]           = se;
        sp[BN + tid]      = pbi[n] - pmu[n] * se;
        sp[2 * BN + tid]  = (MODE == 0) ? pb0[n] : (pb0[n] + pb1[n]);
    }
    __syncthreads();

    const int groupID = lane >> 2;
    const int colPair = (lane & 3) * 2;

    #pragma unroll
    for (int it = 0; it < 4; it++) {
        #pragma unroll
        for (int jt = 0; jt < 8; jt++) {
            int lc = warp_n * 64 + jt * 8 + colPair;
            float se0 = sp[lc],      se1 = sp[lc + 1];
            float of0 = sp[BN+lc],   of1 = sp[BN+lc+1];
            float bb0 = sp[2*BN+lc], bb1 = sp[2*BN+lc+1];
            #pragma unroll
            for (int rr = 0; rr < 2; rr++) {
                int m = blockRow + warp_m * 64 + it * 16 + groupID + rr * 8;
                float v0 = fmaf(fmaxf(acc[it][jt][2*rr]   + bb0, 0.0f), se0, of0);
                float v1 = fmaf(fmaxf(acc[it][jt][2*rr+1] + bb1, 0.0f), se1, of1);
                if (MODE == 0) {
                    __nv_bfloat16 h0, l0, h1, l1;
                    bsplit(v0, h0, l0);
                    bsplit(v1, h1, l1);
                    size_t o = (size_t)m * KD2 + 1024 + blockCol + lc;
                    *reinterpret_cast<__nv_bfloat162*>(&g_A2h[o]) = __halves2bfloat162(h0, h1);
                    *reinterpret_cast<__nv_bfloat162*>(&g_A2l[o]) = __halves2bfloat162(l0, l1);
                } else {
                    size_t o = (size_t)m * NOUT + blockCol + lc;
                    *reinterpret_cast<float2*>(&outp[o]) = make_float2(v0, v1);
                }
            }
        }
    }
}

// ---------------------------------------------------------------------------
// Launch (no static guards — identical work on every call)
// ---------------------------------------------------------------------------
extern "C" void kernel_launch(void* const* d_in, const int* in_sizes, int n_in,
                              void* d_out, int out_size) {
    const float* x    = (const float*)d_in[0];
    const float* q1   = (const float*)d_in[1];   // (2, bs, 512, 1): slice 0
    const float* q2   = (const float*)d_in[2];   // (4, bs, 1024,1): slice 0
    const float* w1   = (const float*)d_in[3];
    const float* b1   = (const float*)d_in[4];
    const float* w2   = (const float*)d_in[5];
    const float* b2   = (const float*)d_in[6];
    const float* wsk  = (const float*)d_in[7];
    const float* bsk  = (const float*)d_in[8];
    const float* s1   = (const float*)d_in[9];
    const float* bi1  = (const float*)d_in[10];
    const float* mu1  = (const float*)d_in[11];
    const float* va1  = (const float*)d_in[12];
    const float* s2   = (const float*)d_in[13];
    const float* bi2  = (const float*)d_in[14];
    const float* mu2  = (const float*)d_in[15];
    const float* va2  = (const float*)d_in[16];
    float* out = (float*)d_out;
    (void)in_sizes; (void)n_in; (void)out_size;

    cudaFuncSetAttribute(gemm_kernel<0>, cudaFuncAttributeMaxDynamicSharedMemorySize, SMEM_BYTES);
    cudaFuncSetAttribute(gemm_kernel<1>, cudaFuncAttributeMaxDynamicSharedMemorySize, SMEM_BYTES);

    pack_all<<<(NPTOT + 255) / 256, 256>>>(q1, x, q2, w1, w2, wsk);

    dim3 g1(NMID / BN, BSZ / BM);   // (8, 64)
    gemm_kernel<0><<<g1, 256, SMEM_BYTES>>>(b1, nullptr, s1, bi1, mu1, va1, nullptr);

    dim3 g2(NOUT / BN, BSZ / BM);   // (4, 64)
    gemm_kernel<1><<<g2, 256, SMEM_BYTES>>>(b2, bsk, s2, bi2, mu2, va2, out);
}